// round 13
// baseline (speedup 1.0000x reference)
#include <cuda_runtime.h>
#include <cuda_fp16.h>
#include <cstdint>

// ---------------- problem constants ----------------
#define Bb   256
#define Tt   512
#define Ii   64
#define Hh   512
#define NTHR 256      // 8 compute warps: 2(M) x 4(N), warp tile M16 x N32

// SMEM layout offsets (from 1024-aligned base)
#define OFF_WH 0          // W_hh slice: [128 c][1024 B] = 128KB
#define OFF_WX 131072     // W_ih slice: [128 c][128 B] = 16KB
#define OFF_H0 147456     // h tile buf0: [512 k][32 r] fp16 = 32KB
#define OFF_H1 180224     // h tile buf1
#define OFF_X0 212992     // x tile buf0: [64 k][32 r] fp16 = 4KB
#define OFF_X1 217088     // x tile buf1
#define DSM_BYTES (221184 + 1024)

// ---------------- persistent device state ----------------
// x tiles: [t][group][4KB], K-major [64 k][32 r], 16B-chunk swizzle
__device__ __align__(1024) unsigned char g_xblk[Tt][8][4096];
// h exchange staging: [group][rank][2KB] — slice = [32 k][32 r] swizzled
__device__ __align__(1024) unsigned char g_hexch[8][16][2048];
__device__ float g_hfinal[Bb][Hh];

// ---------------- PTX helpers ----------------
__device__ __forceinline__ uint32_t smem_u32(const void* p) {
    uint32_t a;
    asm("{ .reg .u64 t; cvta.to.shared.u64 t, %1; cvt.u32.u64 %0, t; }" : "=r"(a) : "l"(p));
    return a;
}
#define MBARRIER_INIT(sa, cnt) \
    asm volatile("mbarrier.init.shared.b64 [%0], %1;" :: "r"((uint32_t)(sa)), "r"((uint32_t)(cnt)) : "memory")
#define MBARRIER_EXPECT_TX(sa, bytes) \
    asm volatile("mbarrier.arrive.expect_tx.shared.b64 _, [%0], %1;" \
                 :: "r"((uint32_t)(sa)), "r"((uint32_t)(bytes)) : "memory")
#define MBAR_WAIT(sa, ph) do { \
    asm volatile("{\n\t.reg .pred P1;\n\tWL%=:\n\t" \
        "mbarrier.try_wait.parity.acquire.cta.shared::cta.b64 P1, [%0], %1, 0x989680;\n\t" \
        "@P1 bra.uni WD%=;\n\tbra.uni WL%=;\n\tWD%=:\n\t}" \
        :: "r"((uint32_t)(sa)), "r"((uint32_t)(ph)) : "memory"); \
} while (0)
#define FENCE_PROXY_ASYNC() asm volatile("fence.proxy.async;" ::: "memory")
#define CLUSTER_SYNC() do { \
    asm volatile("barrier.cluster.arrive.aligned;" ::: "memory"); \
    asm volatile("barrier.cluster.wait.aligned;" ::: "memory"); \
} while (0)

__device__ __forceinline__ void tma_issue(uint32_t dst, const void* src, uint32_t bytes, uint32_t mbar) {
    MBARRIER_EXPECT_TX(mbar, bytes);
    asm volatile("cp.async.bulk.shared::cta.global.mbarrier::complete_tx::bytes [%0], [%1], %2, [%3];"
                 :: "r"(dst), "l"(src), "r"(bytes), "r"(mbar) : "memory");
}
// multicast: one CTA pushes its slice to same offset in all 16 cluster CTAs
__device__ __forceinline__ void tma_mcast(uint32_t dst, const void* src, uint32_t bytes,
                                          uint32_t mbar, uint16_t mask) {
    asm volatile("cp.async.bulk.shared::cluster.global.mbarrier::complete_tx::bytes.multicast::cluster "
                 "[%0], [%1], %2, [%3], %4;"
                 :: "r"(dst), "l"(src), "r"(bytes), "r"(mbar), "h"(mask) : "memory");
}
__device__ __forceinline__ void ldsm4(uint32_t& a, uint32_t& b, uint32_t& c, uint32_t& d, uint32_t addr) {
    asm volatile("ldmatrix.sync.aligned.m8n8.x4.shared.b16 {%0,%1,%2,%3}, [%4];"
                 : "=r"(a), "=r"(b), "=r"(c), "=r"(d) : "r"(addr));
}
__device__ __forceinline__ void ldsm4t(uint32_t& a, uint32_t& b, uint32_t& c, uint32_t& d, uint32_t addr) {
    asm volatile("ldmatrix.sync.aligned.m8n8.x4.trans.shared.b16 {%0,%1,%2,%3}, [%4];"
                 : "=r"(a), "=r"(b), "=r"(c), "=r"(d) : "r"(addr));
}
__device__ __forceinline__ void mma16816(float* c, uint32_t a0, uint32_t a1, uint32_t a2, uint32_t a3,
                                         uint32_t b0, uint32_t b1) {
    asm volatile("mma.sync.aligned.m16n8k16.row.col.f32.f16.f16.f32 "
                 "{%0,%1,%2,%3}, {%4,%5,%6,%7}, {%8,%9}, {%0,%1,%2,%3};"
                 : "+f"(c[0]), "+f"(c[1]), "+f"(c[2]), "+f"(c[3])
                 : "r"(a0), "r"(a1), "r"(a2), "r"(a3), "r"(b0), "r"(b1));
}
__device__ __forceinline__ void mma16816h(uint32_t* c, uint32_t a0, uint32_t a1, uint32_t a2, uint32_t a3,
                                          uint32_t b0, uint32_t b1) {
    asm volatile("mma.sync.aligned.m16n8k16.row.col.f16.f16.f16.f16 "
                 "{%0,%1}, {%2,%3,%4,%5}, {%6,%7}, {%0,%1};"
                 : "+r"(c[0]), "+r"(c[1])
                 : "r"(a0), "r"(a1), "r"(a2), "r"(a3), "r"(b0), "r"(b1));
}

// ---------------- activations ----------------
__device__ __forceinline__ float sigm(float x) { return __fdividef(1.f, 1.f + __expf(-x)); }
__device__ __forceinline__ float tanh_(float x) {
    x = fminf(fmaxf(x, -15.f), 15.f);
    float e = __expf(2.f * x);
    return __fdividef(e - 1.f, e + 1.f);
}

// ---------------- h quarter GEMM: f16 accum, A via trans-ldsm from K-major tile ----------------
__device__ __forceinline__ void compute_h_quarter(uint32_t Hbase, uint32_t WhW, int q,
                                                  uint32_t (&acc16)[4][2], int lane, int m0) {
    const int cB = (lane & 7) + ((lane & 16) >> 1);
    const int kB = (lane >> 3) & 1;
    const int klA = (lane & 7) + ((lane & 16) >> 1);
    const int rbase = m0 + ((lane >> 3) & 1) * 8;
#pragma unroll
    for (int si = 0; si < 8; si++) {
        const int s = q * 8 + si;
        const int kline = s * 16 + klA;
        uint32_t aaddr = Hbase + kline * 64 + ((((rbase >> 3) ^ kline) & 3) << 4);
        uint32_t a[4];
        ldsm4t(a[0], a[1], a[2], a[3], aaddr);
        const int kcW = s * 2;
        uint32_t b01 = WhW + cB * 1024 + (((kcW + kB) ^ (cB & 7)) << 4);
        uint32_t bh[8];
        ldsm4(bh[0], bh[1], bh[2], bh[3], b01);
        ldsm4(bh[4], bh[5], bh[6], bh[7], b01 + 16 * 1024);
#pragma unroll
        for (int ti = 0; ti < 4; ti++)
            mma16816h(acc16[ti], a[0], a[1], a[2], a[3], bh[2 * ti], bh[2 * ti + 1]);
    }
}

// ---------------- x GEMM: f32 accum ----------------
__device__ __forceinline__ void compute_x(uint32_t Xbase, uint32_t WxW,
                                          float (&acc)[4][4], int lane, int m0) {
    const int cB = (lane & 7) + ((lane & 16) >> 1);
    const int kB = (lane >> 3) & 1;
    const int klA = (lane & 7) + ((lane & 16) >> 1);
    const int rbase = m0 + ((lane >> 3) & 1) * 8;
#pragma unroll
    for (int s = 0; s < 4; s++) {
        const int kline = s * 16 + klA;
        uint32_t aaddr = Xbase + kline * 64 + ((((rbase >> 3) ^ kline) & 3) << 4);
        uint32_t a[4];
        ldsm4t(a[0], a[1], a[2], a[3], aaddr);
        uint32_t b01 = WxW + cB * 128 + (((s * 2 + kB) ^ (cB & 7)) << 4);
        uint32_t bh[8];
        ldsm4(bh[0], bh[1], bh[2], bh[3], b01);
        ldsm4(bh[4], bh[5], bh[6], bh[7], b01 + 16 * 128);
#pragma unroll
        for (int ti = 0; ti < 4; ti++)
            mma16816(acc[ti], a[0], a[1], a[2], a[3], bh[2 * ti], bh[2 * ti + 1]);
    }
}

// ---------------- init: x -> fp16 K-major tile layout ----------------
__global__ void init_kernel(const float* __restrict__ x) {
    int idx = blockIdx.x * blockDim.x + threadIdx.x;
    int stride = gridDim.x * blockDim.x;
    for (int i = idx; i < Bb * Tt * Ii; i += stride) {
        int k = i & 63;
        int t = (i >> 6) & 511;
        int b = i >> 15;
        int grp = b >> 5, r = b & 31;
        unsigned off = (unsigned)k * 64u + ((((unsigned)(r >> 3) ^ (unsigned)k) & 3u) << 4) + (r & 7) * 2u;
        *reinterpret_cast<__half*>(&g_xblk[t][grp][off]) = __float2half(x[i]);
    }
}

// ---------------- persistent LSTM: cluster-16, multicast h exchange ----------------
__global__ void __launch_bounds__(NTHR, 1) lstm_kernel(
    const float* __restrict__ W_ih,   // [2048, 64]
    const float* __restrict__ W_hh,   // [2048, 512]
    const float* __restrict__ b_ih,
    const float* __restrict__ b_hh)
{
    extern __shared__ char dsm[];
    // mbars: [0..3] h-quarters buf0, [4..7] h-quarters buf1, [8] x buf0, [9] x buf1
    __shared__ __align__(8) unsigned long long s_mb[10];
    __shared__ float s_bias[128];

    const int tid  = threadIdx.x;
    const int lane = tid & 31;
    const int wid  = tid >> 5;
    const int grp  = blockIdx.x >> 4;       // 8 groups x 32 batch rows
    const int rank = blockIdx.x & 15;       // rank within cluster; gate cols [rank*128, +128)

    uint32_t raw = smem_u32(dsm);
    uint32_t base = (raw + 1023u) & ~1023u;
    char* bptr = dsm + (base - raw);

    // ---- stage W slices (once), fp16, swizzled ----
    for (int idx = tid; idx < 128 * Hh; idx += NTHR) {
        int c = idx >> 9, k = idx & 511;
        int row = (c & 3) * Hh + rank * 32 + (c >> 2);
        float w = W_hh[(size_t)row * Hh + k];
        unsigned off = (unsigned)c * 1024u + ((((unsigned)k >> 3) ^ (c & 7)) << 4) + (k & 7) * 2u;
        *reinterpret_cast<__half*>(bptr + OFF_WH + off) = __float2half(w);
    }
    for (int idx = tid; idx < 128 * Ii; idx += NTHR) {
        int c = idx >> 6, k = idx & 63;
        int row = (c & 3) * Hh + rank * 32 + (c >> 2);
        float w = W_ih[(size_t)row * Ii + k];
        unsigned off = (unsigned)c * 128u + ((((unsigned)k >> 3) ^ (c & 7)) << 4) + (k & 7) * 2u;
        *reinterpret_cast<__half*>(bptr + OFF_WX + off) = __float2half(w);
    }
    if (tid < 128) {
        int row = (tid & 3) * Hh + rank * 32 + (tid >> 2);
        s_bias[tid] = b_ih[row] + b_hh[row];
    }
    if (tid == 0) {
#pragma unroll
        for (int i = 0; i < 10; i++) MBARRIER_INIT(smem_u32(&s_mb[i]), 1);
    }
    __syncthreads();
    CLUSTER_SYNC();   // peer mbars initialized before any multicast lands

    uint32_t hq[2][4], xf[2];
#pragma unroll
    for (int b = 0; b < 2; b++) {
#pragma unroll
        for (int q = 0; q < 4; q++) hq[b][q] = smem_u32(&s_mb[b * 4 + q]);
        xf[b] = smem_u32(&s_mb[8 + b]);
    }
    const uint32_t Hbuf[2] = { base + OFF_H0, base + OFF_H1 };
    const uint32_t Xbuf[2] = { base + OFF_X0, base + OFF_X1 };

    // prologue: x[0], x[1] in flight
    if (tid == 0) {
        tma_issue(Xbuf[0], &g_xblk[0][grp][0], 4096, xf[0]);
        tma_issue(Xbuf[1], &g_xblk[1][grp][0], 4096, xf[1]);
    }

    // ---- warp / thread mapping ----
    const int mh = wid & 1, nq = wid >> 1;  // m0 = mh*16, n0 = nq*32
    const int m0 = mh * 16;
    const uint32_t WhW = base + OFF_WH + nq * 32 * 1024;
    const uint32_t WxW = base + OFF_WX + nq * 32 * 128;

    const int cgrp = lane & 3;
    const int odd  = cgrp & 1;
    const int erow = m0 + (lane >> 2) + (odd ? 8 : 0);   // epilogue row (0..31)
    float bia[4][4];
    int uu[4];
#pragma unroll
    for (int ti = 0; ti < 4; ti++) {
        uu[ti] = nq * 8 + ti * 2 + (cgrp >> 1);          // local unit 0..31
#pragma unroll
        for (int g = 0; g < 4; g++) bia[ti][g] = s_bias[uu[ti] * 4 + g];
    }
    unsigned char* const hstg = &g_hexch[grp][rank][0];

    float cs[4] = {0.f, 0.f, 0.f, 0.f};
    int ph_h[2] = {0, 0}, ph_x[2] = {0, 0};

#pragma unroll 1
    for (int t = 0; t < Tt; t++) {
        const int buf = t & 1;

        float acc[4][4];
#pragma unroll
        for (int a = 0; a < 4; a++)
#pragma unroll
            for (int b = 0; b < 4; b++) acc[a][b] = 0.f;

        // x contribution (f32 accum); buffer issued >= 2 steps ago
        MBAR_WAIT(xf[buf], ph_x[buf]); ph_x[buf] ^= 1;
        compute_x(Xbuf[buf], WxW, acc, lane, m0);

        // h contribution: 4 quarters, f16 accum promoted per quarter (h0 == 0 -> skip at t=0)
        if (t > 0) {
#pragma unroll
            for (int q = 0; q < 4; q++) {
                MBAR_WAIT(hq[buf][q], ph_h[buf]);
                uint32_t a16[4][2];
#pragma unroll
                for (int a = 0; a < 4; a++) { a16[a][0] = 0u; a16[a][1] = 0u; }
                compute_h_quarter(Hbuf[buf], WhW, q, a16, lane, m0);
#pragma unroll
                for (int a = 0; a < 4; a++) {
                    float2 lo = __half22float2(*reinterpret_cast<__half2*>(&a16[a][0]));
                    float2 hi = __half22float2(*reinterpret_cast<__half2*>(&a16[a][1]));
                    acc[a][0] += lo.x; acc[a][1] += lo.y;
                    acc[a][2] += hi.x; acc[a][3] += hi.y;
                }
            }
            ph_h[buf] ^= 1;
        }

        // ---- shuffle epilogue: each thread gets one (row, unit) gate quad per ti ----
#pragma unroll
        for (int ti = 0; ti < 4; ti++) {
            float e0 = __shfl_xor_sync(0xffffffffu, acc[ti][0], 1);
            float e1 = __shfl_xor_sync(0xffffffffu, acc[ti][1], 1);
            float e2 = __shfl_xor_sync(0xffffffffu, acc[ti][2], 1);
            float e3 = __shfl_xor_sync(0xffffffffu, acc[ti][3], 1);
            float gi, gf, gg, go;
            if (odd) { gi = e2;          gf = e3;          gg = acc[ti][2]; go = acc[ti][3]; }
            else     { gi = acc[ti][0];  gf = acc[ti][1];  gg = e0;         go = e1;         }
            float iv = sigm(gi + bia[ti][0]);
            float fv = sigm(gf + bia[ti][1]);
            float gv = tanh_(gg + bia[ti][2]);
            float ov = sigm(go + bia[ti][3]);
            cs[ti] = fv * cs[ti] + iv * gv;
            float hv = ov * tanh_(cs[ti]);
            // staging slice [32 k][32 r], same swizzle as consumer
            int u = uu[ti];
            unsigned off = (unsigned)u * 64u + ((((unsigned)(erow >> 3) ^ (unsigned)u) & 3u) << 4)
                         + (erow & 7) * 2u;
            *reinterpret_cast<unsigned short*>(hstg + off) = __half_as_ushort(__float2half(hv));
            if (t == Tt - 1) g_hfinal[grp * 32 + erow][rank * 32 + u] = hv;
        }

        // ---- push h slice for step t+1 ----
        if (t < Tt - 1) {
            __threadfence();      // STGs visible at GPU scope before TMA reads them
            __syncthreads();
            if (tid == 0) {
                FENCE_PROXY_ASYNC();
                const int nb = (t + 1) & 1;
#pragma unroll
                for (int q = 0; q < 4; q++) MBARRIER_EXPECT_TX(hq[nb][q], 8192);
                tma_mcast(Hbuf[nb] + rank * 2048, hstg, 2048, hq[nb][rank >> 2], (uint16_t)0xFFFFu);
                if (t + 2 < Tt)
                    tma_issue(Xbuf[buf], &g_xblk[t + 2][grp][0], 4096, xf[buf]);
            }
        }
    }

    CLUSTER_SYNC();   // no CTA exits while peers' multicasts may target its SMEM
}

// ---------------- final FC ----------------
__global__ void fc_kernel(const float* __restrict__ W_fc,
                          const float* __restrict__ b_fc,
                          float* __restrict__ out) {
    int b = threadIdx.x;
    float s = 0.f;
#pragma unroll 8
    for (int k = 0; k < Hh; k++) s += g_hfinal[b][k] * W_fc[k];
    out[b] = s + b_fc[0];
}

extern "C" void kernel_launch(void* const* d_in, const int* in_sizes, int n_in,
                              void* d_out, int out_size) {
    const float* x    = (const float*)d_in[0];
    const float* W_ih = (const float*)d_in[1];
    const float* W_hh = (const float*)d_in[2];
    const float* b_ih = (const float*)d_in[3];
    const float* b_hh = (const float*)d_in[4];
    const float* W_fc = (const float*)d_in[5];
    const float* b_fc = (const float*)d_in[6];
    float* out = (float*)d_out;

    cudaFuncSetAttribute(lstm_kernel, cudaFuncAttributeMaxDynamicSharedMemorySize, DSM_BYTES);
    cudaFuncSetAttribute(lstm_kernel, cudaFuncAttributeNonPortableClusterSizeAllowed, 1);

    init_kernel<<<1024, 256>>>(x);

    cudaLaunchConfig_t cfg = {};
    cfg.gridDim = dim3(128, 1, 1);
    cfg.blockDim = dim3(NTHR, 1, 1);
    cfg.dynamicSmemBytes = DSM_BYTES;
    cudaLaunchAttribute attrs[1];
    attrs[0].id = cudaLaunchAttributeClusterDimension;
    attrs[0].val.clusterDim = {16, 1, 1};
    cfg.attrs = attrs;
    cfg.numAttrs = 1;
    cudaLaunchKernelEx(&cfg, lstm_kernel, W_ih, W_hh, b_ih, b_hh);

    fc_kernel<<<1, Bb>>>(W_fc, b_fc, out);
}

// round 14
// speedup vs baseline: 1.4402x; 1.4402x over previous
#include <cuda_runtime.h>
#include <cuda_fp16.h>
#include <cstdint>

// ---------------- problem constants ----------------
#define Bb   256
#define Tt   512
#define Ii   64
#define Hh   512
#define NTHR 288     // 8 compute warps (4M x 2N, warp tile M16xN32) + 1 DMA warp

// SMEM layout offsets (from 1024-aligned base)
#define OFF_WH   0            // W_hh slice (fp16): [64 c][1024 B] = 64KB
#define OFF_WX   65536        // W_ih slice: [64 c][128 B] = 8KB
#define OFF_A    73728        // 4 h chunk bufs, 16KB each (fp16)
#define OFF_XB   139264       // 2 x bufs, 8KB each
#define DSM_BYTES (155648 + 1024)

// ---------------- persistent device state ----------------
// h tile layout: [buf][group][kchunk][16KB]; group = half*2 + mtile (64 batch rows)
// chunk = 64 rows x 128 units fp16 (256B/row), 16B-chunk swizzle
__device__ __align__(1024) unsigned char g_hblk[2][4][4][16384];
// x tile layout: [t][group][8KB] = 64 rows x 64 fp16 (128B/row), swizzled
__device__ __align__(1024) unsigned char g_xblk[Tt][4][8192];
__device__ float    g_hfinal[Bb][Hh];
__device__ unsigned g_cnt[4][4][16];   // [group][kchunk], padded to 64B

// ---------------- PTX helpers ----------------
__device__ __forceinline__ uint32_t smem_u32(const void* p) {
    uint32_t a;
    asm("{ .reg .u64 t; cvta.to.shared.u64 t, %1; cvt.u32.u64 %0, t; }" : "=r"(a) : "l"(p));
    return a;
}
#define MBARRIER_INIT(sa, cnt) \
    asm volatile("mbarrier.init.shared.b64 [%0], %1;" :: "r"((uint32_t)(sa)), "r"((uint32_t)(cnt)) : "memory")
#define MBARRIER_ARRIVE(sa) \
    asm volatile("mbarrier.arrive.shared.b64 _, [%0];" :: "r"((uint32_t)(sa)) : "memory")
#define MBAR_WAIT(sa, ph) do { \
    asm volatile("{\n\t.reg .pred P1;\n\tWL%=:\n\t" \
        "mbarrier.try_wait.parity.acquire.cta.shared::cta.b64 P1, [%0], %1, 0x989680;\n\t" \
        "@P1 bra.uni WD%=;\n\tbra.uni WL%=;\n\tWD%=:\n\t}" \
        :: "r"((uint32_t)(sa)), "r"((uint32_t)(ph)) : "memory"); \
} while (0)
#define FENCE_PROXY_ASYNC() asm volatile("fence.proxy.async;" ::: "memory")

__device__ __forceinline__ void tma_issue(uint32_t dst, const void* src, uint32_t bytes, uint32_t mbar) {
    asm volatile("mbarrier.arrive.expect_tx.shared.b64 _, [%0], %1;"
                 :: "r"(mbar), "r"(bytes) : "memory");
    asm volatile("cp.async.bulk.shared::cta.global.mbarrier::complete_tx::bytes [%0], [%1], %2, [%3];"
                 :: "r"(dst), "l"(src), "r"(bytes), "r"(mbar) : "memory");
}
__device__ __forceinline__ void ldsm4(uint32_t& a, uint32_t& b, uint32_t& c, uint32_t& d, uint32_t addr) {
    asm volatile("ldmatrix.sync.aligned.m8n8.x4.shared.b16 {%0,%1,%2,%3}, [%4];"
                 : "=r"(a), "=r"(b), "=r"(c), "=r"(d) : "r"(addr));
}
// f32-accum fp16 MMA (x chunk)
__device__ __forceinline__ void mma16816(float* c, uint32_t a0, uint32_t a1, uint32_t a2, uint32_t a3,
                                         uint32_t b0, uint32_t b1) {
    asm volatile("mma.sync.aligned.m16n8k16.row.col.f32.f16.f16.f32 "
                 "{%0,%1,%2,%3}, {%4,%5,%6,%7}, {%8,%9}, {%0,%1,%2,%3};"
                 : "+f"(c[0]), "+f"(c[1]), "+f"(c[2]), "+f"(c[3])
                 : "r"(a0), "r"(a1), "r"(a2), "r"(a3), "r"(b0), "r"(b1));
}
// f16-accum fp16 MMA (h chunks)
__device__ __forceinline__ void mma16816h(uint32_t* c, uint32_t a0, uint32_t a1, uint32_t a2, uint32_t a3,
                                          uint32_t b0, uint32_t b1) {
    asm volatile("mma.sync.aligned.m16n8k16.row.col.f16.f16.f16.f16 "
                 "{%0,%1}, {%2,%3,%4,%5}, {%6,%7}, {%0,%1};"
                 : "+r"(c[0]), "+r"(c[1])
                 : "r"(a0), "r"(a1), "r"(a2), "r"(a3), "r"(b0), "r"(b1));
}
#define BAR_COMPUTE() asm volatile("bar.sync 1, 256;" ::: "memory")

// ---------------- activations ----------------
__device__ __forceinline__ float sigm(float x) { return __fdividef(1.f, 1.f + __expf(-x)); }
__device__ __forceinline__ float tanh_(float x) {
    x = fminf(fmaxf(x, -15.f), 15.f);
    float e = __expf(2.f * x);
    return __fdividef(e - 1.f, e + 1.f);
}

// ---------------- h-chunk GEMM: fp16 accum, warp tile M16xN32 ----------------
// A tile [64 rows x 128 k] fp16 (256B rows); W rows 1024B (base at warp's N slab).
__device__ __forceinline__ void compute_chunk_h16(uint32_t Abase, uint32_t Whi,
                                                  int kw0, uint32_t (&acc16)[4][2],
                                                  int lane, int m0) {
    const int rA = m0 + (lane & 15);
    const int kA = lane >> 4;
    const int xr = lane & 7;
    const int cB = (lane & 7) + ((lane & 16) >> 1);
    const int kB = (lane >> 3) & 1;
#pragma unroll
    for (int s = 0; s < 8; s++) {
        const int kcA = s * 2;
        uint32_t aaddr = Abase + rA * 256 + (((kcA + kA) ^ xr) << 4);
        uint32_t a[4];
        ldsm4(a[0], a[1], a[2], a[3], aaddr);
        const int kcW = kw0 + s * 2;
        uint32_t b01 = Whi + cB * 1024 + (((kcW + kB) ^ xr) << 4);
        uint32_t bh[8];
        ldsm4(bh[0], bh[1], bh[2], bh[3], b01);
        ldsm4(bh[4], bh[5], bh[6], bh[7], b01 + 16 * 1024);
#pragma unroll
        for (int ti = 0; ti < 4; ti++)
            mma16816h(acc16[ti], a[0], a[1], a[2], a[3], bh[2 * ti], bh[2 * ti + 1]);
    }
}

// ---------------- x-chunk GEMM: f32 accum ----------------
__device__ __forceinline__ void compute_x(uint32_t Abase, uint32_t Whi,
                                          float (&acc)[4][4], int lane, int m0) {
    const int rA = m0 + (lane & 15);
    const int kA = lane >> 4;
    const int xr = lane & 7;
    const int cB = (lane & 7) + ((lane & 16) >> 1);
    const int kB = (lane >> 3) & 1;
#pragma unroll
    for (int s = 0; s < 4; s++) {
        uint32_t aaddr = Abase + rA * 128 + (((s * 2 + kA) ^ xr) << 4);
        uint32_t a[4];
        ldsm4(a[0], a[1], a[2], a[3], aaddr);
        uint32_t b01 = Whi + cB * 128 + (((s * 2 + kB) ^ xr) << 4);
        uint32_t bh[8];
        ldsm4(bh[0], bh[1], bh[2], bh[3], b01);
        ldsm4(bh[4], bh[5], bh[6], bh[7], b01 + 16 * 128);
#pragma unroll
        for (int ti = 0; ti < 4; ti++)
            mma16816(acc[ti], a[0], a[1], a[2], a[3], bh[2 * ti], bh[2 * ti + 1]);
    }
}

// ---------------- init: zero h buf0, reset counters, x -> fp16 tile layout ----------------
__global__ void init_kernel(const float* __restrict__ x) {
    int idx = blockIdx.x * blockDim.x + threadIdx.x;
    int stride = gridDim.x * blockDim.x;
    uint32_t* hz = reinterpret_cast<uint32_t*>(&g_hblk[0][0][0][0]);
    for (int i = idx; i < 4 * 4 * 16384 / 4; i += stride) hz[i] = 0u;
    for (int i = idx; i < Bb * Tt * Ii; i += stride) {
        int ii = i & 63;
        int t  = (i >> 6) & 511;
        int b  = i >> 15;
        int grp = b >> 6, m = b & 63;
        unsigned off = (unsigned)m * 128u + ((((unsigned)ii >> 3) ^ (m & 7)) << 4) + (ii & 7) * 2u;
        *reinterpret_cast<__half*>(&g_xblk[t][grp][off]) = __float2half(x[i]);
    }
    if (idx < 16) g_cnt[idx >> 2][idx & 3][0] = 0u;
}

// ---------------- persistent LSTM: parallel-DMA lanes, shuffle epilogue ----------------
__global__ void __launch_bounds__(NTHR, 1) lstm_kernel(
    const float* __restrict__ W_ih,   // [2048, 64]
    const float* __restrict__ W_hh,   // [2048, 512]
    const float* __restrict__ b_ih,
    const float* __restrict__ b_hh)
{
    extern __shared__ char dsm[];
    // mbars: 0..3 full A[kc], 4..5 full X[buf], 6..9 empty A[kc], 10..11 empty X[buf]
    __shared__ __align__(8) unsigned long long s_mb[12];
    __shared__ float s_bias[64];

    const int tid  = threadIdx.x;
    const int lane = tid & 31;
    const int wid  = tid >> 5;
    const int grp  = blockIdx.x >> 5;       // owns 64 batch rows
    const int nc   = blockIdx.x & 31;       // gate cols [nc*64, nc*64+64) -> 16 units

    uint32_t raw = smem_u32(dsm);
    uint32_t base = (raw + 1023u) & ~1023u;
    char* bptr = dsm + (base - raw);

    // ---- stage W slices (once), fp16, swizzled ----
    for (int idx = tid; idx < 64 * Hh; idx += NTHR) {
        int c = idx >> 9, k = idx & 511;
        int row = (c & 3) * Hh + nc * 16 + (c >> 2);
        float w = W_hh[(size_t)row * Hh + k];
        unsigned off = (unsigned)c * 1024u + ((((unsigned)k >> 3) ^ (c & 7)) << 4) + (k & 7) * 2u;
        *reinterpret_cast<__half*>(bptr + OFF_WH + off) = __float2half(w);
    }
    for (int idx = tid; idx < 64 * Ii; idx += NTHR) {
        int c = idx >> 6, k = idx & 63;
        int row = (c & 3) * Hh + nc * 16 + (c >> 2);
        float w = W_ih[(size_t)row * Ii + k];
        unsigned off = (unsigned)c * 128u + ((((unsigned)k >> 3) ^ (c & 7)) << 4) + (k & 7) * 2u;
        *reinterpret_cast<__half*>(bptr + OFF_WX + off) = __float2half(w);
    }
    if (tid < 64) {
        int row = (tid & 3) * Hh + nc * 16 + (tid >> 2);
        s_bias[tid] = b_ih[row] + b_hh[row];
    }
    if (tid == 0) {
#pragma unroll
        for (int i = 0; i < 6; i++)  MBARRIER_INIT(smem_u32(&s_mb[i]), 1);   // full (expect_tx)
#pragma unroll
        for (int i = 6; i < 12; i++) MBARRIER_INIT(smem_u32(&s_mb[i]), 8);   // empty (8 warps)
    }
    __syncthreads();

    uint32_t fA[4], eA[4], fx[2], ex[2];
#pragma unroll
    for (int i = 0; i < 4; i++) { fA[i] = smem_u32(&s_mb[i]); eA[i] = smem_u32(&s_mb[6 + i]); }
#pragma unroll
    for (int i = 0; i < 2; i++) { fx[i] = smem_u32(&s_mb[4 + i]); ex[i] = smem_u32(&s_mb[10 + i]); }
    uint32_t Abuf[4];
#pragma unroll
    for (int i = 0; i < 4; i++) Abuf[i] = base + OFF_A + i * 16384;
    const uint32_t Xbuf[2] = { base + OFF_XB, base + OFF_XB + 8192 };

    // =========================== DMA warp: lanes 0-3 own h chunks, lane 4 owns x ===========================
    if (wid == 8) {
        if (lane < 4) {
            volatile unsigned* cnt = &g_cnt[grp][lane][0];
            int pe = 1;
#pragma unroll 1
            for (int t = 0; t < Tt; t++) {
                const unsigned char* hsrc = &g_hblk[t & 1][grp][lane][0];
                const unsigned target = (unsigned)t * 8u;
                MBAR_WAIT(eA[lane], pe); pe ^= 1;
                unsigned v;
                do {
                    asm volatile("ld.acquire.gpu.global.u32 %0, [%1];" : "=r"(v) : "l"(cnt));
                } while (v < target);
                FENCE_PROXY_ASYNC();
                tma_issue(Abuf[lane], hsrc, 16384, fA[lane]);
            }
        } else if (lane == 4) {
            int pe[2] = {1, 1};
#pragma unroll 1
            for (int t = 0; t < Tt; t++) {
                const int b = t & 1;
                MBAR_WAIT(ex[b], pe[b]); pe[b] ^= 1;
                FENCE_PROXY_ASYNC();
                tma_issue(Xbuf[b], &g_xblk[t][grp][0], 8192, fx[b]);
            }
        }
        return;
    }

    // =========================== compute warps: 4(M) x 2(N), warp tile M16xN32 ===========================
    const int m0 = (wid >> 1) * 16;
    const int nh = wid & 1;
    const uint32_t WhW = base + OFF_WH + nh * 32 * 1024;
    const uint32_t WxW = base + OFF_WX + nh * 32 * 128;

    // shuffle-epilogue mapping: thread -> 1 row x 4 units
    const int cgrp = lane & 3;
    const int odd  = cgrp & 1;
    const int erow = m0 + (lane >> 2) + (odd ? 8 : 0);   // local batch row 0..63
    int uloc[4];
    float bia[4][4];
#pragma unroll
    for (int ti = 0; ti < 4; ti++) {
        uloc[ti] = nh * 8 + ti * 2 + (cgrp >> 1);        // local unit 0..15
#pragma unroll
        for (int g = 0; g < 4; g++) bia[ti][g] = s_bias[uloc[ti] * 4 + g];
    }
    // h store addresses (chunk kcb = nc>>3 fixed per CTA)
    const int kcb = nc >> 3;
    unsigned hoff[4];
#pragma unroll
    for (int ti = 0; ti < 4; ti++) {
        unsigned ucol = (unsigned)((nc & 7) * 16 + uloc[ti]);
        hoff[ti] = (unsigned)erow * 256u + (((ucol >> 3) ^ (erow & 7)) << 4) + (ucol & 7) * 2u;
    }
    unsigned* mycnt = &g_cnt[grp][kcb][0];

    float cs[4] = {0.f, 0.f, 0.f, 0.f};
    int pfA[4] = {0, 0, 0, 0}, pfx[2] = {0, 0};

#pragma unroll 1
    for (int t = 0; t < Tt; t++) {
        const int wb = (t & 1) ^ 1;
        const int xb = t & 1;

        float acc[4][4];
#pragma unroll
        for (int a = 0; a < 4; a++)
#pragma unroll
            for (int b = 0; b < 4; b++) acc[a][b] = 0.f;

        // x chunk first (f32 accum) — double-buffered, prefetched a step ahead
        MBAR_WAIT(fx[xb], pfx[xb]); pfx[xb] ^= 1;
        compute_x(Xbuf[xb], WxW, acc, lane, m0);
        if (lane == 0) MBARRIER_ARRIVE(ex[xb]);

        // h chunks: fp16 accum per chunk, promote to f32
#pragma unroll
        for (int kc = 0; kc < 4; kc++) {
            MBAR_WAIT(fA[kc], pfA[kc]); pfA[kc] ^= 1;
            uint32_t a16[4][2];
#pragma unroll
            for (int a = 0; a < 4; a++) { a16[a][0] = 0u; a16[a][1] = 0u; }
            compute_chunk_h16(Abuf[kc], WhW, kc * 16, a16, lane, m0);
            if (lane == 0) MBARRIER_ARRIVE(eA[kc]);
#pragma unroll
            for (int a = 0; a < 4; a++) {
                float2 lo = __half22float2(*reinterpret_cast<__half2*>(&a16[a][0]));
                float2 hi = __half22float2(*reinterpret_cast<__half2*>(&a16[a][1]));
                acc[a][0] += lo.x; acc[a][1] += lo.y;
                acc[a][2] += hi.x; acc[a][3] += hi.y;
            }
        }

        // ---- shuffle epilogue: one (row, unit-quad) per thread per ti ----
        unsigned char* const hdst = &g_hblk[wb][grp][kcb][0];
#pragma unroll
        for (int ti = 0; ti < 4; ti++) {
            float e0 = __shfl_xor_sync(0xffffffffu, acc[ti][0], 1);
            float e1 = __shfl_xor_sync(0xffffffffu, acc[ti][1], 1);
            float e2 = __shfl_xor_sync(0xffffffffu, acc[ti][2], 1);
            float e3 = __shfl_xor_sync(0xffffffffu, acc[ti][3], 1);
            float gi, gf, gg, go;
            if (odd) { gi = e2;         gf = e3;         gg = acc[ti][2]; go = acc[ti][3]; }
            else     { gi = acc[ti][0]; gf = acc[ti][1]; gg = e0;         go = e1;         }
            float iv = sigm(gi + bia[ti][0]);
            float fv = sigm(gf + bia[ti][1]);
            float gv = tanh_(gg + bia[ti][2]);
            float ov = sigm(go + bia[ti][3]);
            cs[ti] = fv * cs[ti] + iv * gv;
            float hv = ov * tanh_(cs[ti]);
            *reinterpret_cast<unsigned short*>(hdst + hoff[ti]) = __half_as_ushort(__float2half(hv));
            if (t == Tt - 1) g_hfinal[grp * 64 + erow][nc * 16 + uloc[ti]] = hv;
        }

        BAR_COMPUTE();     // all compute warps' h STGs done
        if (tid == 0 && t < Tt - 1)
            asm volatile("red.release.gpu.global.add.u32 [%0], %1;" :: "l"(mycnt), "r"(1u) : "memory");
    }
}

// ---------------- final FC ----------------
__global__ void fc_kernel(const float* __restrict__ W_fc,
                          const float* __restrict__ b_fc,
                          float* __restrict__ out) {
    int b = threadIdx.x;
    float s = 0.f;
#pragma unroll 8
    for (int k = 0; k < Hh; k++) s += g_hfinal[b][k] * W_fc[k];
    out[b] = s + b_fc[0];
}

extern "C" void kernel_launch(void* const* d_in, const int* in_sizes, int n_in,
                              void* d_out, int out_size) {
    const float* x    = (const float*)d_in[0];
    const float* W_ih = (const float*)d_in[1];
    const float* W_hh = (const float*)d_in[2];
    const float* b_ih = (const float*)d_in[3];
    const float* b_hh = (const float*)d_in[4];
    const float* W_fc = (const float*)d_in[5];
    const float* b_fc = (const float*)d_in[6];
    float* out = (float*)d_out;

    cudaFuncSetAttribute(lstm_kernel, cudaFuncAttributeMaxDynamicSharedMemorySize, DSM_BYTES);

    init_kernel<<<1024, 256>>>(x);
    lstm_kernel<<<128, NTHR, DSM_BYTES>>>(W_ih, W_hh, b_ih, b_hh);
    fc_kernel<<<1, Bb>>>(W_fc, b_fc, out);
}

// round 15
// speedup vs baseline: 1.5684x; 1.0890x over previous
#include <cuda_runtime.h>
#include <cuda_fp16.h>
#include <cstdint>

// ---------------- problem constants ----------------
#define Bb   256
#define Tt   512
#define Ii   64
#define Hh   512
#define NTHR 160     // 4 compute warps (2M x 2N, warp tile M16xN32) + 1 DMA warp

// SMEM layout offsets (from 1024-aligned base)
#define OFF_WH   0            // W_hh slice (fp16): [64 c][1024 B] = 64KB
#define OFF_WX   65536        // W_ih slice: [64 c][128 B] = 8KB
#define OFF_A    73728        // 4 h chunk bufs, 8KB each (fp16, 32 rows x 256B)
#define OFF_XB   106496       // x buf: 4KB (32 rows x 128B)
#define DSM_BYTES (110592 + 1024)

// ---------------- persistent device state ----------------
// h tile layout: [buf][group][kchunk][8KB]; group = 32 batch rows (8 groups)
// chunk = 32 rows x 128 units fp16 (256B/row), 16B-chunk swizzle
__device__ __align__(1024) unsigned char g_hblk[2][8][4][8192];
// x tile layout: [t][group][4KB] = 32 rows x 64 fp16 (128B/row), swizzled
__device__ __align__(1024) unsigned char g_xblk[Tt][8][4096];
__device__ float    g_hfinal[Bb][Hh];
__device__ unsigned g_cnt[8][4][16];   // [group][kchunk], padded to 64B

// ---------------- PTX helpers ----------------
__device__ __forceinline__ uint32_t smem_u32(const void* p) {
    uint32_t a;
    asm("{ .reg .u64 t; cvta.to.shared.u64 t, %1; cvt.u32.u64 %0, t; }" : "=r"(a) : "l"(p));
    return a;
}
#define MBARRIER_INIT(sa, cnt) \
    asm volatile("mbarrier.init.shared.b64 [%0], %1;" :: "r"((uint32_t)(sa)), "r"((uint32_t)(cnt)) : "memory")
#define MBARRIER_ARRIVE(sa) \
    asm volatile("mbarrier.arrive.shared.b64 _, [%0];" :: "r"((uint32_t)(sa)) : "memory")
#define MBAR_WAIT(sa, ph) do { \
    asm volatile("{\n\t.reg .pred P1;\n\tWL%=:\n\t" \
        "mbarrier.try_wait.parity.acquire.cta.shared::cta.b64 P1, [%0], %1, 0x989680;\n\t" \
        "@P1 bra.uni WD%=;\n\tbra.uni WL%=;\n\tWD%=:\n\t}" \
        :: "r"((uint32_t)(sa)), "r"((uint32_t)(ph)) : "memory"); \
} while (0)
#define FENCE_PROXY_ASYNC() asm volatile("fence.proxy.async;" ::: "memory")

__device__ __forceinline__ void tma_issue(uint32_t dst, const void* src, uint32_t bytes, uint32_t mbar) {
    asm volatile("mbarrier.arrive.expect_tx.shared.b64 _, [%0], %1;"
                 :: "r"(mbar), "r"(bytes) : "memory");
    asm volatile("cp.async.bulk.shared::cta.global.mbarrier::complete_tx::bytes [%0], [%1], %2, [%3];"
                 :: "r"(dst), "l"(src), "r"(bytes), "r"(mbar) : "memory");
}
__device__ __forceinline__ void ldsm4(uint32_t& a, uint32_t& b, uint32_t& c, uint32_t& d, uint32_t addr) {
    asm volatile("ldmatrix.sync.aligned.m8n8.x4.shared.b16 {%0,%1,%2,%3}, [%4];"
                 : "=r"(a), "=r"(b), "=r"(c), "=r"(d) : "r"(addr));
}
// f32-accum fp16 MMA (x chunk)
__device__ __forceinline__ void mma16816(float* c, uint32_t a0, uint32_t a1, uint32_t a2, uint32_t a3,
                                         uint32_t b0, uint32_t b1) {
    asm volatile("mma.sync.aligned.m16n8k16.row.col.f32.f16.f16.f32 "
                 "{%0,%1,%2,%3}, {%4,%5,%6,%7}, {%8,%9}, {%0,%1,%2,%3};"
                 : "+f"(c[0]), "+f"(c[1]), "+f"(c[2]), "+f"(c[3])
                 : "r"(a0), "r"(a1), "r"(a2), "r"(a3), "r"(b0), "r"(b1));
}
// f16-accum fp16 MMA (h chunks)
__device__ __forceinline__ void mma16816h(uint32_t* c, uint32_t a0, uint32_t a1, uint32_t a2, uint32_t a3,
                                          uint32_t b0, uint32_t b1) {
    asm volatile("mma.sync.aligned.m16n8k16.row.col.f16.f16.f16.f16 "
                 "{%0,%1}, {%2,%3,%4,%5}, {%6,%7}, {%0,%1};"
                 : "+r"(c[0]), "+r"(c[1])
                 : "r"(a0), "r"(a1), "r"(a2), "r"(a3), "r"(b0), "r"(b1));
}
#define BAR_COMPUTE() asm volatile("bar.sync 1, 128;" ::: "memory")

// ---------------- activations ----------------
__device__ __forceinline__ float sigm(float x) { return __fdividef(1.f, 1.f + __expf(-x)); }
__device__ __forceinline__ float tanh_(float x) {
    x = fminf(fmaxf(x, -15.f), 15.f);
    float e = __expf(2.f * x);
    return __fdividef(e - 1.f, e + 1.f);
}

// ---------------- h-chunk GEMM: fp16 accum, warp tile M16xN32 ----------------
// A tile [32 rows x 128 k] fp16 (256B rows); W rows 1024B (base at warp's N slab).
__device__ __forceinline__ void compute_chunk_h16(uint32_t Abase, uint32_t Whi,
                                                  int kw0, uint32_t (&acc16)[4][2],
                                                  int lane, int m0) {
    const int rA = m0 + (lane & 15);
    const int kA = lane >> 4;
    const int xr = lane & 7;
    const int cB = (lane & 7) + ((lane & 16) >> 1);
    const int kB = (lane >> 3) & 1;
#pragma unroll
    for (int s = 0; s < 8; s++) {
        const int kcA = s * 2;
        uint32_t aaddr = Abase + rA * 256 + (((kcA + kA) ^ xr) << 4);
        uint32_t a[4];
        ldsm4(a[0], a[1], a[2], a[3], aaddr);
        const int kcW = kw0 + s * 2;
        uint32_t b01 = Whi + cB * 1024 + (((kcW + kB) ^ xr) << 4);
        uint32_t bh[8];
        ldsm4(bh[0], bh[1], bh[2], bh[3], b01);
        ldsm4(bh[4], bh[5], bh[6], bh[7], b01 + 16 * 1024);
#pragma unroll
        for (int ti = 0; ti < 4; ti++)
            mma16816h(acc16[ti], a[0], a[1], a[2], a[3], bh[2 * ti], bh[2 * ti + 1]);
    }
}

// ---------------- x-chunk GEMM: f32 accum ----------------
__device__ __forceinline__ void compute_x(uint32_t Abase, uint32_t Whi,
                                          float (&acc)[4][4], int lane, int m0) {
    const int rA = m0 + (lane & 15);
    const int kA = lane >> 4;
    const int xr = lane & 7;
    const int cB = (lane & 7) + ((lane & 16) >> 1);
    const int kB = (lane >> 3) & 1;
#pragma unroll
    for (int s = 0; s < 4; s++) {
        uint32_t aaddr = Abase + rA * 128 + (((s * 2 + kA) ^ xr) << 4);
        uint32_t a[4];
        ldsm4(a[0], a[1], a[2], a[3], aaddr);
        uint32_t b01 = Whi + cB * 128 + (((s * 2 + kB) ^ xr) << 4);
        uint32_t bh[8];
        ldsm4(bh[0], bh[1], bh[2], bh[3], b01);
        ldsm4(bh[4], bh[5], bh[6], bh[7], b01 + 16 * 128);
#pragma unroll
        for (int ti = 0; ti < 4; ti++)
            mma16816(acc[ti], a[0], a[1], a[2], a[3], bh[2 * ti], bh[2 * ti + 1]);
    }
}

// ---------------- init: zero h buf0, reset counters, x -> fp16 tile layout ----------------
__global__ void init_kernel(const float* __restrict__ x) {
    int idx = blockIdx.x * blockDim.x + threadIdx.x;
    int stride = gridDim.x * blockDim.x;
    uint32_t* hz = reinterpret_cast<uint32_t*>(&g_hblk[0][0][0][0]);
    for (int i = idx; i < 8 * 4 * 8192 / 4; i += stride) hz[i] = 0u;
    for (int i = idx; i < Bb * Tt * Ii; i += stride) {
        int ii = i & 63;
        int t  = (i >> 6) & 511;
        int b  = i >> 15;
        int grp = b >> 5, m = b & 31;
        unsigned off = (unsigned)m * 128u + ((((unsigned)ii >> 3) ^ (m & 7)) << 4) + (ii & 7) * 2u;
        *reinterpret_cast<__half*>(&g_xblk[t][grp][off]) = __float2half(x[i]);
    }
    if (idx < 32) g_cnt[idx >> 2][idx & 3][0] = 0u;
}

// ---------------- persistent LSTM: occupancy-2 latency hiding ----------------
__global__ void __launch_bounds__(NTHR, 2) lstm_kernel(
    const float* __restrict__ W_ih,   // [2048, 64]
    const float* __restrict__ W_hh,   // [2048, 512]
    const float* __restrict__ b_ih,
    const float* __restrict__ b_hh)
{
    extern __shared__ char dsm[];
    // mbars: 0..3 full A[kc], 4 full X, 5..8 empty A[kc], 9 empty X
    __shared__ __align__(8) unsigned long long s_mb[10];
    __shared__ float s_bias[64];

    const int tid  = threadIdx.x;
    const int lane = tid & 31;
    const int wid  = tid >> 5;
    const int grp  = blockIdx.x >> 5;       // 8 groups x 32 batch rows
    const int nc   = blockIdx.x & 31;       // gate cols [nc*64, nc*64+64) -> 16 units

    uint32_t raw = smem_u32(dsm);
    uint32_t base = (raw + 1023u) & ~1023u;
    char* bptr = dsm + (base - raw);

    // ---- stage W slices (once), fp16, swizzled ----
    for (int idx = tid; idx < 64 * Hh; idx += NTHR) {
        int c = idx >> 9, k = idx & 511;
        int row = (c & 3) * Hh + nc * 16 + (c >> 2);
        float w = W_hh[(size_t)row * Hh + k];
        unsigned off = (unsigned)c * 1024u + ((((unsigned)k >> 3) ^ (c & 7)) << 4) + (k & 7) * 2u;
        *reinterpret_cast<__half*>(bptr + OFF_WH + off) = __float2half(w);
    }
    for (int idx = tid; idx < 64 * Ii; idx += NTHR) {
        int c = idx >> 6, k = idx & 63;
        int row = (c & 3) * Hh + nc * 16 + (c >> 2);
        float w = W_ih[(size_t)row * Ii + k];
        unsigned off = (unsigned)c * 128u + ((((unsigned)k >> 3) ^ (c & 7)) << 4) + (k & 7) * 2u;
        *reinterpret_cast<__half*>(bptr + OFF_WX + off) = __float2half(w);
    }
    if (tid < 64) {
        int row = (tid & 3) * Hh + nc * 16 + (tid >> 2);
        s_bias[tid] = b_ih[row] + b_hh[row];
    }
    if (tid == 0) {
#pragma unroll
        for (int i = 0; i < 5; i++)  MBARRIER_INIT(smem_u32(&s_mb[i]), 1);   // full (expect_tx)
#pragma unroll
        for (int i = 5; i < 10; i++) MBARRIER_INIT(smem_u32(&s_mb[i]), 4);   // empty (4 compute warps)
    }
    __syncthreads();

    uint32_t fA[4], eA[4];
#pragma unroll
    for (int i = 0; i < 4; i++) { fA[i] = smem_u32(&s_mb[i]); eA[i] = smem_u32(&s_mb[5 + i]); }
    const uint32_t fx = smem_u32(&s_mb[4]), ex = smem_u32(&s_mb[9]);
    uint32_t Abuf[4];
#pragma unroll
    for (int i = 0; i < 4; i++) Abuf[i] = base + OFF_A + i * 8192;
    const uint32_t XB = base + OFF_XB;

    // =========================== DMA warp: lanes 0-3 own h chunks, lane 4 owns x ===========================
    if (wid == 4) {
        if (lane < 4) {
            volatile unsigned* cnt = &g_cnt[grp][lane][0];
            int pe = 1;
#pragma unroll 1
            for (int t = 0; t < Tt; t++) {
                const unsigned char* hsrc = &g_hblk[t & 1][grp][lane][0];
                const unsigned target = (unsigned)t * 8u;
                MBAR_WAIT(eA[lane], pe); pe ^= 1;
                unsigned v;
                do {
                    asm volatile("ld.acquire.gpu.global.u32 %0, [%1];" : "=r"(v) : "l"(cnt));
                } while (v < target);
                FENCE_PROXY_ASYNC();
                tma_issue(Abuf[lane], hsrc, 8192, fA[lane]);
            }
        } else if (lane == 4) {
            int pe = 1;
#pragma unroll 1
            for (int t = 0; t < Tt; t++) {
                MBAR_WAIT(ex, pe); pe ^= 1;
                FENCE_PROXY_ASYNC();
                tma_issue(XB, &g_xblk[t][grp][0], 4096, fx);
            }
        }
        return;
    }

    // =========================== compute warps: 2(M) x 2(N), warp tile M16xN32 ===========================
    const int m0 = (wid >> 1) * 16;
    const int nh = wid & 1;
    const uint32_t WhW = base + OFF_WH + nh * 32 * 1024;
    const uint32_t WxW = base + OFF_WX + nh * 32 * 128;

    // shuffle-epilogue mapping: thread -> 1 row x 4 unit-quads
    const int cgrp = lane & 3;
    const int odd  = cgrp & 1;
    const int erow = m0 + (lane >> 2) + (odd ? 8 : 0);   // local batch row 0..31
    int uloc[4];
    float bia[4][4];
#pragma unroll
    for (int ti = 0; ti < 4; ti++) {
        uloc[ti] = nh * 8 + ti * 2 + (cgrp >> 1);        // local unit 0..15
#pragma unroll
        for (int g = 0; g < 4; g++) bia[ti][g] = s_bias[uloc[ti] * 4 + g];
    }
    // h store addresses (chunk kcb = nc>>3 fixed per CTA)
    const int kcb = nc >> 3;
    unsigned hoff[4];
#pragma unroll
    for (int ti = 0; ti < 4; ti++) {
        unsigned ucol = (unsigned)((nc & 7) * 16 + uloc[ti]);
        hoff[ti] = (unsigned)erow * 256u + (((ucol >> 3) ^ (erow & 7)) << 4) + (ucol & 7) * 2u;
    }
    unsigned* mycnt = &g_cnt[grp][kcb][0];

    float cs[4] = {0.f, 0.f, 0.f, 0.f};
    int pfA[4] = {0, 0, 0, 0}, pfx = 0;

#pragma unroll 1
    for (int t = 0; t < Tt; t++) {
        const int wb = (t & 1) ^ 1;

        float acc[4][4];
#pragma unroll
        for (int a = 0; a < 4; a++)
#pragma unroll
            for (int b = 0; b < 4; b++) acc[a][b] = 0.f;

        // x chunk first (f32 accum)
        MBAR_WAIT(fx, pfx); pfx ^= 1;
        compute_x(XB, WxW, acc, lane, m0);
        if (lane == 0) MBARRIER_ARRIVE(ex);

        // h chunks: fp16 accum per chunk, promote to f32
#pragma unroll
        for (int kc = 0; kc < 4; kc++) {
            MBAR_WAIT(fA[kc], pfA[kc]); pfA[kc] ^= 1;
            uint32_t a16[4][2];
#pragma unroll
            for (int a = 0; a < 4; a++) { a16[a][0] = 0u; a16[a][1] = 0u; }
            compute_chunk_h16(Abuf[kc], WhW, kc * 16, a16, lane, m0);
            if (lane == 0) MBARRIER_ARRIVE(eA[kc]);
#pragma unroll
            for (int a = 0; a < 4; a++) {
                float2 lo = __half22float2(*reinterpret_cast<__half2*>(&a16[a][0]));
                float2 hi = __half22float2(*reinterpret_cast<__half2*>(&a16[a][1]));
                acc[a][0] += lo.x; acc[a][1] += lo.y;
                acc[a][2] += hi.x; acc[a][3] += hi.y;
            }
        }

        // ---- shuffle epilogue: one (row, unit-quad) per thread per ti ----
        unsigned char* const hdst = &g_hblk[wb][grp][kcb][0];
#pragma unroll
        for (int ti = 0; ti < 4; ti++) {
            float e0 = __shfl_xor_sync(0xffffffffu, acc[ti][0], 1);
            float e1 = __shfl_xor_sync(0xffffffffu, acc[ti][1], 1);
            float e2 = __shfl_xor_sync(0xffffffffu, acc[ti][2], 1);
            float e3 = __shfl_xor_sync(0xffffffffu, acc[ti][3], 1);
            float gi, gf, gg, go;
            if (odd) { gi = e2;         gf = e3;         gg = acc[ti][2]; go = acc[ti][3]; }
            else     { gi = acc[ti][0]; gf = acc[ti][1]; gg = e0;         go = e1;         }
            float iv = sigm(gi + bia[ti][0]);
            float fv = sigm(gf + bia[ti][1]);
            float gv = tanh_(gg + bia[ti][2]);
            float ov = sigm(go + bia[ti][3]);
            cs[ti] = fv * cs[ti] + iv * gv;
            float hv = ov * tanh_(cs[ti]);
            *reinterpret_cast<unsigned short*>(hdst + hoff[ti]) = __half_as_ushort(__float2half(hv));
            if (t == Tt - 1) g_hfinal[grp * 32 + erow][nc * 16 + uloc[ti]] = hv;
        }

        BAR_COMPUTE();     // all compute warps' h STGs done
        if (tid == 0 && t < Tt - 1)
            asm volatile("red.release.gpu.global.add.u32 [%0], %1;" :: "l"(mycnt), "r"(1u) : "memory");
    }
}

// ---------------- final FC ----------------
__global__ void fc_kernel(const float* __restrict__ W_fc,
                          const float* __restrict__ b_fc,
                          float* __restrict__ out) {
    int b = threadIdx.x;
    float s = 0.f;
#pragma unroll 8
    for (int k = 0; k < Hh; k++) s += g_hfinal[b][k] * W_fc[k];
    out[b] = s + b_fc[0];
}

extern "C" void kernel_launch(void* const* d_in, const int* in_sizes, int n_in,
                              void* d_out, int out_size) {
    const float* x    = (const float*)d_in[0];
    const float* W_ih = (const float*)d_in[1];
    const float* W_hh = (const float*)d_in[2];
    const float* b_ih = (const float*)d_in[3];
    const float* b_hh = (const float*)d_in[4];
    const float* W_fc = (const float*)d_in[5];
    const float* b_fc = (const float*)d_in[6];
    float* out = (float*)d_out;

    cudaFuncSetAttribute(lstm_kernel, cudaFuncAttributeMaxDynamicSharedMemorySize, DSM_BYTES);

    init_kernel<<<1024, 256>>>(x);
    lstm_kernel<<<256, NTHR, DSM_BYTES>>>(W_ih, W_hh, b_ih, b_hh);
    fc_kernel<<<1, Bb>>>(W_fc, b_fc, out);
}